// round 1
// baseline (speedup 1.0000x reference)
#include <cuda_runtime.h>

// Problem constants
#define NN   10368          // N = 18*24*24
#define CC   512            // channels
#define HS   128            // hidden size
#define M1   256            // stacked [Wi;Wj] rows
#define PCH  18             // split-K chunks for T
#define CHUNK 576           // NN / PCH

// Scratch (no allocations allowed in kernel_launch)
__device__ float g_f[M1 * NN];              // f = [fi; fj], row-major [256][NN]
__device__ float g_Tpart[PCH * HS * CC];    // split-K partials of T
__device__ float g_T[HS * CC];              // T = fj @ x^T   [128][512]

// ---------------------------------------------------------------------------
// K1: f[m][n] = sum_c W[m][c] * x[c][n] + b[m],  M=256, K=512, N=NN
// Tiles 64x64, BK=16, 256 threads, 4x4 per thread.
// ---------------------------------------------------------------------------
__global__ __launch_bounds__(256) void k1_f(const float* __restrict__ Wi,
                                            const float* __restrict__ bi,
                                            const float* __restrict__ Wj,
                                            const float* __restrict__ bj,
                                            const float* __restrict__ x) {
    __shared__ float As[16][68];   // [k][m]
    __shared__ float Bs[16][68];   // [k][n]
    const int m0 = blockIdx.y * 64;
    const int n0 = blockIdx.x * 64;
    const float* A    = (m0 < HS) ? (Wi + m0 * CC) : (Wj + (m0 - HS) * CC);
    const float* bptr = (m0 < HS) ? (bi + m0)      : (bj + (m0 - HS));

    const int tid = threadIdx.x;
    const int ar = tid >> 2, ac = (tid & 3) << 2;     // A: 64 rows x 16 k
    const int br = tid >> 4, bc = (tid & 15) << 2;    // B: 16 k x 64 n
    const int ty = tid >> 4, tx = tid & 15;

    float acc[4][4] = {};
    for (int k0 = 0; k0 < CC; k0 += 16) {
        float4 av = *(const float4*)(A + ar * CC + k0 + ac);
        As[ac + 0][ar] = av.x; As[ac + 1][ar] = av.y;
        As[ac + 2][ar] = av.z; As[ac + 3][ar] = av.w;
        float4 bv = *(const float4*)(x + (size_t)(k0 + br) * NN + n0 + bc);
        Bs[br][bc + 0] = bv.x; Bs[br][bc + 1] = bv.y;
        Bs[br][bc + 2] = bv.z; Bs[br][bc + 3] = bv.w;
        __syncthreads();
#pragma unroll
        for (int kk = 0; kk < 16; kk++) {
            float a[4], b[4];
#pragma unroll
            for (int i = 0; i < 4; i++) a[i] = As[kk][ty * 4 + i];
#pragma unroll
            for (int j = 0; j < 4; j++) b[j] = Bs[kk][tx * 4 + j];
#pragma unroll
            for (int i = 0; i < 4; i++)
#pragma unroll
                for (int j = 0; j < 4; j++) acc[i][j] += a[i] * b[j];
        }
        __syncthreads();
    }
#pragma unroll
    for (int i = 0; i < 4; i++) {
        const float bias = bptr[ty * 4 + i];
        const int m = m0 + ty * 4 + i;
#pragma unroll
        for (int j = 0; j < 4; j++)
            g_f[(size_t)m * NN + n0 + tx * 4 + j] = acc[i][j] + bias;
    }
}

// ---------------------------------------------------------------------------
// K2: Tpart[p][h][c] = sum_{n in chunk p} fj[h][n] * x[c][n]   (NT gemm)
// grid (CC/64, HS/64, PCH)
// ---------------------------------------------------------------------------
__global__ __launch_bounds__(256) void k2_tpart(const float* __restrict__ x) {
    __shared__ float As[16][68];   // [k(n)][h]
    __shared__ float Bs[16][68];   // [k(n)][c]
    const int c0 = blockIdx.x * 64;
    const int h0 = blockIdx.y * 64;
    const int p  = blockIdx.z;
    const float* A = g_f + (size_t)(HS + h0) * NN + p * CHUNK;  // fj rows
    const float* B = x + (size_t)c0 * NN + p * CHUNK;           // x rows

    const int tid = threadIdx.x;
    const int ar = tid >> 2, ac = (tid & 3) << 2;   // 64 rows x 16 n, both operands
    const int ty = tid >> 4, tx = tid & 15;

    float acc[4][4] = {};
    for (int k0 = 0; k0 < CHUNK; k0 += 16) {
        float4 av = *(const float4*)(A + (size_t)ar * NN + k0 + ac);
        As[ac + 0][ar] = av.x; As[ac + 1][ar] = av.y;
        As[ac + 2][ar] = av.z; As[ac + 3][ar] = av.w;
        float4 bv = *(const float4*)(B + (size_t)ar * NN + k0 + ac);
        Bs[ac + 0][ar] = bv.x; Bs[ac + 1][ar] = bv.y;
        Bs[ac + 2][ar] = bv.z; Bs[ac + 3][ar] = bv.w;
        __syncthreads();
#pragma unroll
        for (int kk = 0; kk < 16; kk++) {
            float a[4], b[4];
#pragma unroll
            for (int i = 0; i < 4; i++) a[i] = As[kk][ty * 4 + i];
#pragma unroll
            for (int j = 0; j < 4; j++) b[j] = Bs[kk][tx * 4 + j];
#pragma unroll
            for (int i = 0; i < 4; i++)
#pragma unroll
                for (int j = 0; j < 4; j++) acc[i][j] += a[i] * b[j];
        }
        __syncthreads();
    }
    float* out = g_Tpart + (size_t)p * HS * CC;
#pragma unroll
    for (int i = 0; i < 4; i++)
#pragma unroll
        for (int j = 0; j < 4; j++)
            out[(h0 + ty * 4 + i) * CC + c0 + tx * 4 + j] = acc[i][j];
}

// ---------------------------------------------------------------------------
// K3: T = sum_p Tpart[p]
// ---------------------------------------------------------------------------
__global__ void k3_reduce() {
    int i = blockIdx.x * 256 + threadIdx.x;
    if (i < HS * CC) {
        float s = 0.f;
#pragma unroll
        for (int p = 0; p < PCH; p++) s += g_Tpart[(size_t)p * HS * CC + i];
        g_T[i] = s;
    }
}

// ---------------------------------------------------------------------------
// K4: out[c][n] = x[c][n] + scale * sum_h T[h][c] * fi[h][n]
// M=512(c), N=NN(n), K=128(h).  grid (NN/64, CC/64)
// ---------------------------------------------------------------------------
__global__ __launch_bounds__(256) void k4_out(const float* __restrict__ x,
                                              const float* __restrict__ agg,
                                              float* __restrict__ out) {
    __shared__ float As[16][68];   // [k(h)][c]
    __shared__ float Bs[16][68];   // [k(h)][n]
    const int n0 = blockIdx.x * 64;
    const int c0 = blockIdx.y * 64;

    const int tid = threadIdx.x;
    const int r = tid >> 4, col = (tid & 15) << 2;   // 16 k-rows x 64 cols
    const int ty = tid >> 4, tx = tid & 15;

    float acc[4][4] = {};
    for (int k0 = 0; k0 < HS; k0 += 16) {
        float4 av = *(const float4*)(g_T + (size_t)(k0 + r) * CC + c0 + col);
        As[r][col + 0] = av.x; As[r][col + 1] = av.y;
        As[r][col + 2] = av.z; As[r][col + 3] = av.w;
        float4 bv = *(const float4*)(g_f + (size_t)(k0 + r) * NN + n0 + col);
        Bs[r][col + 0] = bv.x; Bs[r][col + 1] = bv.y;
        Bs[r][col + 2] = bv.z; Bs[r][col + 3] = bv.w;
        __syncthreads();
#pragma unroll
        for (int kk = 0; kk < 16; kk++) {
            float a[4], b[4];
#pragma unroll
            for (int i = 0; i < 4; i++) a[i] = As[kk][ty * 4 + i];
#pragma unroll
            for (int j = 0; j < 4; j++) b[j] = Bs[kk][tx * 4 + j];
#pragma unroll
            for (int i = 0; i < 4; i++)
#pragma unroll
                for (int j = 0; j < 4; j++) acc[i][j] += a[i] * b[j];
        }
        __syncthreads();
    }
    const float scale = agg[0] * (1.0f / (float)NN);
#pragma unroll
    for (int i = 0; i < 4; i++) {
        const int c = c0 + ty * 4 + i;
#pragma unroll
        for (int j = 0; j < 4; j++) {
            const int n = n0 + tx * 4 + j;
            out[(size_t)c * NN + n] = x[(size_t)c * NN + n] + scale * acc[i][j];
        }
    }
}

// ---------------------------------------------------------------------------
extern "C" void kernel_launch(void* const* d_in, const int* in_sizes, int n_in,
                              void* d_out, int out_size) {
    const float* features = (const float*)d_in[0];   // [512][10368]
    const float* Wi       = (const float*)d_in[1];   // [128][512]
    const float* bi       = (const float*)d_in[2];   // [128]
    const float* Wj       = (const float*)d_in[3];   // [128][512]
    const float* bj       = (const float*)d_in[4];   // [128]
    const float* agg      = (const float*)d_in[5];   // [1][1]
    float* out = (float*)d_out;

    dim3 g1(NN / 64, M1 / 64);
    k1_f<<<g1, 256>>>(Wi, bi, Wj, bj, features);

    dim3 g2(CC / 64, HS / 64, PCH);
    k2_tpart<<<g2, 256>>>(features);

    k3_reduce<<<(HS * CC + 255) / 256, 256>>>();

    dim3 g4(NN / 64, CC / 64);
    k4_out<<<g4, 256>>>(features, agg, out);
}

// round 3
// speedup vs baseline: 2.7230x; 2.7230x over previous
#include <cuda_runtime.h>
#include <cuda_bf16.h>
#include <cstdint>

#define NN   10368
#define CC   512
#define HS   128
#define SPL  27          // split-K chunks for T
#define KSP  384         // NN / SPL

// ---------------- device scratch ----------------
__device__ __nv_bfloat16 g_Wcat[256 * CC];        // [256][512] K-major (k=c)
__device__ __nv_bfloat16 g_xb[CC * NN];           // x bf16 [512][10368] (k=n for k2)
__device__ __nv_bfloat16 g_xbT[NN * CC];          // x^T bf16 [10368][512] (k=c for k1 B)
__device__ __nv_bfloat16 g_fiT[NN * HS];          // fi^T [10368][128] (k=h for k4 A)
__device__ __nv_bfloat16 g_fj[HS * NN];           // fj [128][10368] (k=n for k2 A)
__device__ float         g_Tpart[SPL * HS * CC];  // split-K partials
__device__ __nv_bfloat16 g_Tt[CC * HS];           // T^T [512][128] (k=h for k4 B)

// ---------------- mma helpers ----------------
__device__ __forceinline__ uint32_t smem_u32(const void* p) {
    uint32_t a;
    asm("{ .reg .u64 t; cvta.to.shared.u64 t, %1; cvt.u32.u64 %0, t; }" : "=r"(a) : "l"(p));
    return a;
}
__device__ __forceinline__ void ldsm4(uint32_t addr, uint32_t& r0, uint32_t& r1,
                                      uint32_t& r2, uint32_t& r3) {
    asm volatile("ldmatrix.sync.aligned.m8n8.x4.shared.b16 {%0,%1,%2,%3}, [%4];"
                 : "=r"(r0), "=r"(r1), "=r"(r2), "=r"(r3) : "r"(addr));
}
__device__ __forceinline__ void mma_bf16(float* c, uint32_t a0, uint32_t a1, uint32_t a2,
                                         uint32_t a3, uint32_t b0, uint32_t b1) {
    asm volatile("mma.sync.aligned.m16n8k16.row.col.f32.bf16.bf16.f32 "
                 "{%0,%1,%2,%3}, {%4,%5,%6,%7}, {%8,%9}, {%0,%1,%2,%3};"
                 : "+f"(c[0]), "+f"(c[1]), "+f"(c[2]), "+f"(c[3])
                 : "r"(a0), "r"(a1), "r"(a2), "r"(a3), "r"(b0), "r"(b1));
}

#define SM_STRIDE 72   // bf16 elems per smem row (64 + 8 pad)

// Shared gemm core: CTA 128x128, warp tile 64m x 32n, BK=64, K-major operands.
// acc[mf][nf][4]
__device__ __forceinline__ void gemm_core(const __nv_bfloat16* __restrict__ Ag, size_t lda,
                                          const __nv_bfloat16* __restrict__ Bg, size_t ldb,
                                          int K, float acc[4][4][4],
                                          __nv_bfloat16* smA, __nv_bfloat16* smB) {
    const int tid = threadIdx.x, lane = tid & 31, wid = tid >> 5;
    const int mBase = (wid >> 2) * 64, nBase = (wid & 3) * 32;

    const uint32_t sa = smem_u32(smA), sb = smem_u32(smB);
    const int a_r = lane & 15, a_k = (lane >> 4) * 8;
    const int b_r = ((lane >> 4) << 3) + (lane & 7), b_k = ((lane >> 3) & 1) * 8;
    const uint32_t aB = sa + (uint32_t)((mBase + a_r) * SM_STRIDE + a_k) * 2;
    const uint32_t bB = sb + (uint32_t)((nBase + b_r) * SM_STRIDE + b_k) * 2;

    for (int k0 = 0; k0 < K; k0 += 64) {
#pragma unroll
        for (int i = tid; i < 1024; i += 256) {
            const int row = i >> 3, kq = (i & 7) * 8;
            *(uint4*)(smA + row * SM_STRIDE + kq) = *(const uint4*)(Ag + (size_t)row * lda + k0 + kq);
            *(uint4*)(smB + row * SM_STRIDE + kq) = *(const uint4*)(Bg + (size_t)row * ldb + k0 + kq);
        }
        __syncthreads();
#pragma unroll
        for (int kk = 0; kk < 4; kk++) {
            uint32_t af[4][4], bf[2][4];
#pragma unroll
            for (int mf = 0; mf < 4; mf++)
                ldsm4(aB + (uint32_t)(mf * 16 * SM_STRIDE + kk * 16) * 2,
                      af[mf][0], af[mf][1], af[mf][2], af[mf][3]);
#pragma unroll
            for (int nq = 0; nq < 2; nq++)
                ldsm4(bB + (uint32_t)(nq * 16 * SM_STRIDE + kk * 16) * 2,
                      bf[nq][0], bf[nq][1], bf[nq][2], bf[nq][3]);
#pragma unroll
            for (int mf = 0; mf < 4; mf++)
#pragma unroll
                for (int nq = 0; nq < 2; nq++) {
                    mma_bf16(acc[mf][nq * 2],     af[mf][0], af[mf][1], af[mf][2], af[mf][3],
                             bf[nq][0], bf[nq][1]);
                    mma_bf16(acc[mf][nq * 2 + 1], af[mf][0], af[mf][1], af[mf][2], af[mf][3],
                             bf[nq][2], bf[nq][3]);
                }
        }
        __syncthreads();
    }
}

// ---------------- k0: weights -> bf16 concat ----------------
__global__ void k0_w(const float* __restrict__ Wi, const float* __restrict__ Wj) {
    int i = blockIdx.x * 256 + threadIdx.x;
    if (i < 256 * CC)
        g_Wcat[i] = __float2bfloat16(i < HS * CC ? Wi[i] : Wj[i - HS * CC]);
}

// ---------------- prepass: x -> bf16 + bf16 transpose ----------------
__global__ void k_pre(const float* __restrict__ x) {
    __shared__ float t[32][33];
    const int n0 = blockIdx.x * 32, c0 = blockIdx.y * 32;
    const int tx = threadIdx.x, ty = threadIdx.y;
#pragma unroll
    for (int i = 0; i < 4; i++) {
        int r = ty + i * 8;
        float v = x[(size_t)(c0 + r) * NN + n0 + tx];
        t[r][tx] = v;
        g_xb[(size_t)(c0 + r) * NN + n0 + tx] = __float2bfloat16(v);
    }
    __syncthreads();
#pragma unroll
    for (int i = 0; i < 4; i++) {
        int r = ty + i * 8;
        g_xbT[(size_t)(n0 + r) * CC + c0 + tx] = __float2bfloat16(t[tx][r]);
    }
}

// ---------------- k1: f = Wcat @ x^T^T  (M=256, N=NN, K=512) ----------------
// grid (81 n-tiles, 2 m-tiles)
__global__ __launch_bounds__(256) void k1(const float* __restrict__ bi,
                                          const float* __restrict__ bj) {
    __shared__ __align__(16) __nv_bfloat16 smA[128 * SM_STRIDE];
    __shared__ __align__(16) __nv_bfloat16 smB[128 * SM_STRIDE];
    const int n0 = blockIdx.x * 128, m0 = blockIdx.y * 128;
    float acc[4][4][4] = {};
    gemm_core(g_Wcat + (size_t)m0 * CC, CC, g_xbT + (size_t)n0 * CC, CC, CC, acc, smA, smB);

    const int tid = threadIdx.x, lane = tid & 31, wid = tid >> 5;
    const int mBase = (wid >> 2) * 64, nBase = (wid & 3) * 32;
    const int r = lane >> 2, cc = (lane & 3) * 2;
    const float* bsrc = (m0 == 0) ? bi : bj;
#pragma unroll
    for (int mf = 0; mf < 4; mf++) {
#pragma unroll
        for (int e = 0; e < 2; e++) {   // e: m row / m row + 8
            const int m = mBase + mf * 16 + r + e * 8;
            const float bias = bsrc[m];
#pragma unroll
            for (int nf = 0; nf < 4; nf++) {
                const int n = n0 + nBase + nf * 8 + cc;
                const float v0 = acc[mf][nf][e * 2] + bias;
                const float v1 = acc[mf][nf][e * 2 + 1] + bias;
                if (m0 == 0) {   // fi -> transposed [n][h]
                    g_fiT[(size_t)n * HS + m]       = __float2bfloat16(v0);
                    g_fiT[(size_t)(n + 1) * HS + m] = __float2bfloat16(v1);
                } else {         // fj -> row-major [h][n]
                    *(__nv_bfloat162*)(g_fj + (size_t)m * NN + n) =
                        __floats2bfloat162_rn(v0, v1);
                }
            }
        }
    }
}

// ---------------- k2: Tpart[s] = fj[:, chunk] @ xb[:, chunk]^T ----------------
// M=128(h), N=512(c) in 4 tiles, K=KSP per split.  grid (4 c-tiles, SPL)
__global__ __launch_bounds__(256) void k2() {
    __shared__ __align__(16) __nv_bfloat16 smA[128 * SM_STRIDE];
    __shared__ __align__(16) __nv_bfloat16 smB[128 * SM_STRIDE];
    const int c0 = blockIdx.x * 128, sp = blockIdx.y;
    const size_t koff = (size_t)sp * KSP;
    float acc[4][4][4] = {};
    gemm_core(g_fj + koff, NN, g_xb + (size_t)c0 * NN + koff, NN, KSP, acc, smA, smB);

    const int tid = threadIdx.x, lane = tid & 31, wid = tid >> 5;
    const int mBase = (wid >> 2) * 64, nBase = (wid & 3) * 32;
    const int r = lane >> 2, cc = (lane & 3) * 2;
    float* dst = g_Tpart + (size_t)sp * HS * CC;
#pragma unroll
    for (int mf = 0; mf < 4; mf++)
#pragma unroll
        for (int e = 0; e < 2; e++) {
            const int h = mBase + mf * 16 + r + e * 8;
#pragma unroll
            for (int nf = 0; nf < 4; nf++) {
                const int c = c0 + nBase + nf * 8 + cc;
                *(float2*)(dst + (size_t)h * CC + c) =
                    make_float2(acc[mf][nf][e * 2], acc[mf][nf][e * 2 + 1]);
            }
        }
}

// ---------------- reduce: Tt[c][h] = bf16(sum_s Tpart) ----------------
__global__ void kred() {
    int i = blockIdx.x * 256 + threadIdx.x;   // i = h*512 + c
    if (i < HS * CC) {
        float s = 0.f;
#pragma unroll 9
        for (int p = 0; p < SPL; p++) s += g_Tpart[(size_t)p * HS * CC + i];
        int h = i >> 9, c = i & 511;
        g_Tt[(size_t)c * HS + h] = __float2bfloat16(s);
    }
}

// ---------------- k4: out[c][n] = x[c][n] + scale * (fiT @ Tt^T)[n][c] ----------------
// M=128 n-rows per tile (81 tiles), N=512(c) in 4 tiles, K=128(h). grid (81, 4)
__global__ __launch_bounds__(256) void k4(const float* __restrict__ x,
                                          const float* __restrict__ agg,
                                          float* __restrict__ out) {
    __shared__ __align__(16) __nv_bfloat16 smA[128 * SM_STRIDE];
    __shared__ __align__(16) __nv_bfloat16 smB[128 * SM_STRIDE];
    const int n0 = blockIdx.x * 128, c0 = blockIdx.y * 128;
    float acc[4][4][4] = {};
    gemm_core(g_fiT + (size_t)n0 * HS, HS, g_Tt + (size_t)c0 * HS, HS, HS, acc, smA, smB);

    const int tid = threadIdx.x, lane = tid & 31, wid = tid >> 5;
    const int mBase = (wid >> 2) * 64, nBase = (wid & 3) * 32;
    const int r = lane >> 2, cc = (lane & 3) * 2;
    const float scale = agg[0] * (1.0f / (float)NN);
#pragma unroll
    for (int mf = 0; mf < 4; mf++)
#pragma unroll
        for (int e = 0; e < 2; e++) {
            const int n = n0 + mBase + mf * 16 + r + e * 8;
#pragma unroll
            for (int nf = 0; nf < 4; nf++) {
                const int c = c0 + nBase + nf * 8 + cc;
                const size_t i0 = (size_t)c * NN + n;
                const size_t i1 = (size_t)(c + 1) * NN + n;
                out[i0] = x[i0] + scale * acc[mf][nf][e * 2];
                out[i1] = x[i1] + scale * acc[mf][nf][e * 2 + 1];
            }
        }
}

// ---------------- launch ----------------
extern "C" void kernel_launch(void* const* d_in, const int* in_sizes, int n_in,
                              void* d_out, int out_size) {
    const float* features = (const float*)d_in[0];
    const float* Wi       = (const float*)d_in[1];
    const float* bi       = (const float*)d_in[2];
    const float* Wj       = (const float*)d_in[3];
    const float* bj       = (const float*)d_in[4];
    const float* agg      = (const float*)d_in[5];
    float* out = (float*)d_out;

    k0_w<<<512, 256>>>(Wi, Wj);
    k_pre<<<dim3(NN / 32, CC / 32), dim3(32, 8)>>>(features);
    k1<<<dim3(81, 2), 256>>>(bi, bj);
    k2<<<dim3(4, SPL), 256>>>();
    kred<<<(HS * CC + 255) / 256, 256>>>();
    k4<<<dim3(81, 4), 256>>>(features, agg, out);
}

// round 4
// speedup vs baseline: 2.9158x; 1.0708x over previous
#include <cuda_runtime.h>
#include <cuda_bf16.h>
#include <cstdint>

#define NN   10368
#define CC   512
#define HS   128
#define SPL  81          // split-K chunks for T
#define KSP  128         // NN / SPL

// ---------------- device scratch ----------------
__device__ __nv_bfloat16 g_Wcat[256 * CC];
__device__ __nv_bfloat16 g_xb[CC * NN];
__device__ __nv_bfloat16 g_xbT[NN * CC];
__device__ __nv_bfloat16 g_fiT[NN * HS];
__device__ __nv_bfloat16 g_fj[HS * NN];
__device__ float         g_Tpart[SPL * HS * CC];
__device__ __nv_bfloat16 g_Tt[CC * HS];

// ---------------- helpers ----------------
__device__ __forceinline__ uint32_t smem_u32(const void* p) {
    uint32_t a;
    asm("{ .reg .u64 t; cvta.to.shared.u64 t, %1; cvt.u32.u64 %0, t; }" : "=r"(a) : "l"(p));
    return a;
}
__device__ __forceinline__ void ldsm4(uint32_t addr, uint32_t& r0, uint32_t& r1,
                                      uint32_t& r2, uint32_t& r3) {
    asm volatile("ldmatrix.sync.aligned.m8n8.x4.shared.b16 {%0,%1,%2,%3}, [%4];"
                 : "=r"(r0), "=r"(r1), "=r"(r2), "=r"(r3) : "r"(addr));
}
__device__ __forceinline__ void mma_bf16(float* c, uint32_t a0, uint32_t a1, uint32_t a2,
                                         uint32_t a3, uint32_t b0, uint32_t b1) {
    asm volatile("mma.sync.aligned.m16n8k16.row.col.f32.bf16.bf16.f32 "
                 "{%0,%1,%2,%3}, {%4,%5,%6,%7}, {%8,%9}, {%0,%1,%2,%3};"
                 : "+f"(c[0]), "+f"(c[1]), "+f"(c[2]), "+f"(c[3])
                 : "r"(a0), "r"(a1), "r"(a2), "r"(a3), "r"(b0), "r"(b1));
}
#define CP16(dst, src)  asm volatile("cp.async.cg.shared.global [%0], [%1], 16;" :: "r"(dst), "l"(src))
#define CP_COMMIT()     asm volatile("cp.async.commit_group;" ::: "memory")
#define CP_WAIT0()      asm volatile("cp.async.wait_group 0;" ::: "memory")

#define SM_STRIDE 72                         // bf16/row (64 + 8 pad)
#define STAGE_OP  (128 * SM_STRIDE * 2)      // bytes per operand per stage (18432)
#define STAGE_SZ  (2 * STAGE_OP)             // A + B per stage
#define SMEM_TOT  (2 * STAGE_SZ)             // 73728 bytes

// Pipelined gemm core: CTA 128x128, warp 64m x 32n, BK=64, K-major operands,
// 2-stage cp.async double buffer.
__device__ __forceinline__ void gemm_pipe(const __nv_bfloat16* __restrict__ Ag, size_t lda,
                                          const __nv_bfloat16* __restrict__ Bg, size_t ldb,
                                          int K, float acc[4][4][4], char* sm) {
    const int tid = threadIdx.x, lane = tid & 31, wid = tid >> 5;
    const int mBase = (wid >> 2) * 64, nBase = (wid & 3) * 32;
    const uint32_t sbase = smem_u32(sm);

    const int a_r = lane & 15, a_k = (lane >> 4) * 8;
    const int b_r = ((lane >> 4) << 3) + (lane & 7), b_k = ((lane >> 3) & 1) * 8;
    const uint32_t aOff = (uint32_t)((mBase + a_r) * SM_STRIDE + a_k) * 2;
    const uint32_t bOff = (uint32_t)(STAGE_OP + ((nBase + b_r) * SM_STRIDE + b_k) * 2);

    // per-thread load slots: 8 iters x 16B, split A/B
    const int nstages = K / 64;

    auto load_stage = [&](int s, int k0) {
        const uint32_t st = sbase + s * STAGE_SZ;
#pragma unroll
        for (int i = tid; i < 2048; i += 256) {
            const int which = i >> 10, idx = i & 1023;
            const int row = idx >> 3, q = (idx & 7) * 8;
            const uint32_t dst = st + which * STAGE_OP + (uint32_t)(row * SM_STRIDE + q) * 2;
            const __nv_bfloat16* src = which ? (Bg + (size_t)row * ldb + k0 + q)
                                             : (Ag + (size_t)row * lda + k0 + q);
            CP16(dst, src);
        }
    };

    load_stage(0, 0);
    CP_COMMIT();
    int cur = 0;
    for (int s = 1; s <= nstages; s++) {
        CP_WAIT0();
        __syncthreads();
        if (s < nstages) { load_stage(cur ^ 1, s * 64); CP_COMMIT(); }
        const uint32_t stA = sbase + cur * STAGE_SZ + aOff;
        const uint32_t stB = sbase + cur * STAGE_SZ + bOff;
#pragma unroll
        for (int kk = 0; kk < 4; kk++) {
            uint32_t af[4][4], bf[2][4];
#pragma unroll
            for (int mf = 0; mf < 4; mf++)
                ldsm4(stA + (uint32_t)(mf * 16 * SM_STRIDE + kk * 16) * 2,
                      af[mf][0], af[mf][1], af[mf][2], af[mf][3]);
#pragma unroll
            for (int nq = 0; nq < 2; nq++)
                ldsm4(stB + (uint32_t)(nq * 16 * SM_STRIDE + kk * 16) * 2,
                      bf[nq][0], bf[nq][1], bf[nq][2], bf[nq][3]);
#pragma unroll
            for (int mf = 0; mf < 4; mf++)
#pragma unroll
                for (int nq = 0; nq < 2; nq++) {
                    mma_bf16(acc[mf][nq * 2],     af[mf][0], af[mf][1], af[mf][2], af[mf][3],
                             bf[nq][0], bf[nq][1]);
                    mma_bf16(acc[mf][nq * 2 + 1], af[mf][0], af[mf][1], af[mf][2], af[mf][3],
                             bf[nq][2], bf[nq][3]);
                }
        }
        __syncthreads();
        cur ^= 1;
    }
}

// ---------------- k0: weights -> bf16 concat ----------------
__global__ void k0_w(const float* __restrict__ Wi, const float* __restrict__ Wj) {
    int i = blockIdx.x * 256 + threadIdx.x;
    if (i < 256 * CC)
        g_Wcat[i] = __float2bfloat16(i < HS * CC ? Wi[i] : Wj[i - HS * CC]);
}

// ---------------- prepass: x -> bf16 + bf16 transpose ----------------
__global__ void k_pre(const float* __restrict__ x) {
    __shared__ float t[32][33];
    const int n0 = blockIdx.x * 32, c0 = blockIdx.y * 32;
    const int tx = threadIdx.x, ty = threadIdx.y;
#pragma unroll
    for (int i = 0; i < 4; i++) {
        int r = ty + i * 8;
        float v = x[(size_t)(c0 + r) * NN + n0 + tx];
        t[r][tx] = v;
        g_xb[(size_t)(c0 + r) * NN + n0 + tx] = __float2bfloat16(v);
    }
    __syncthreads();
#pragma unroll
    for (int i = 0; i < 4; i++) {
        int r = ty + i * 8;
        g_xbT[(size_t)(n0 + r) * CC + c0 + tx] = __float2bfloat16(t[tx][r]);
    }
}

// ---------------- k1: f = Wcat @ x  (M=256, N=NN, K=512). grid (81, 2) ----------------
__global__ __launch_bounds__(256) void k1(const float* __restrict__ bi,
                                          const float* __restrict__ bj) {
    extern __shared__ __align__(16) char sm[];
    const int n0 = blockIdx.x * 128, m0 = blockIdx.y * 128;
    float acc[4][4][4] = {};
    gemm_pipe(g_Wcat + (size_t)m0 * CC, CC, g_xbT + (size_t)n0 * CC, CC, CC, acc, sm);

    const int tid = threadIdx.x, lane = tid & 31, wid = tid >> 5;
    const int mBase = (wid >> 2) * 64, nBase = (wid & 3) * 32;
    const int r = lane >> 2, cc = (lane & 3) * 2;
    const float* bsrc = (m0 == 0) ? bi : bj;
#pragma unroll
    for (int mf = 0; mf < 4; mf++)
#pragma unroll
        for (int e = 0; e < 2; e++) {
            const int m = mBase + mf * 16 + r + e * 8;
            const float bias = bsrc[m];
#pragma unroll
            for (int nf = 0; nf < 4; nf++) {
                const int n = n0 + nBase + nf * 8 + cc;
                const float v0 = acc[mf][nf][e * 2] + bias;
                const float v1 = acc[mf][nf][e * 2 + 1] + bias;
                if (m0 == 0) {
                    g_fiT[(size_t)n * HS + m]       = __float2bfloat16(v0);
                    g_fiT[(size_t)(n + 1) * HS + m] = __float2bfloat16(v1);
                } else {
                    *(__nv_bfloat162*)(g_fj + (size_t)m * NN + n) =
                        __floats2bfloat162_rn(v0, v1);
                }
            }
        }
}

// ---------------- k2: Tpart[s] = fj @ xb^T per chunk. grid (4, SPL) ----------------
__global__ __launch_bounds__(256) void k2() {
    extern __shared__ __align__(16) char sm[];
    const int c0 = blockIdx.x * 128, sp = blockIdx.y;
    const size_t koff = (size_t)sp * KSP;
    float acc[4][4][4] = {};
    gemm_pipe(g_fj + koff, NN, g_xb + (size_t)c0 * NN + koff, NN, KSP, acc, sm);

    const int tid = threadIdx.x, lane = tid & 31, wid = tid >> 5;
    const int mBase = (wid >> 2) * 64, nBase = (wid & 3) * 32;
    const int r = lane >> 2, cc = (lane & 3) * 2;
    float* dst = g_Tpart + (size_t)sp * HS * CC;
#pragma unroll
    for (int mf = 0; mf < 4; mf++)
#pragma unroll
        for (int e = 0; e < 2; e++) {
            const int h = mBase + mf * 16 + r + e * 8;
#pragma unroll
            for (int nf = 0; nf < 4; nf++) {
                const int c = c0 + nBase + nf * 8 + cc;
                *(float2*)(dst + (size_t)h * CC + c) =
                    make_float2(acc[mf][nf][e * 2], acc[mf][nf][e * 2 + 1]);
            }
        }
}

// ---------------- reduce: Tt[c][h] = bf16(sum_s Tpart) ----------------
__global__ void kred() {
    int i = blockIdx.x * 256 + threadIdx.x;   // i = h*512 + c
    if (i < HS * CC) {
        float s = 0.f;
        for (int p = 0; p < SPL; p++) s += g_Tpart[(size_t)p * HS * CC + i];
        int h = i >> 9, c = i & 511;
        g_Tt[(size_t)c * HS + h] = __float2bfloat16(s);
    }
}

// ---------------- k4: out = x + scale * (fiT @ Tt^T)^T. grid (81, 4) ----------------
__global__ __launch_bounds__(256) void k4(const float* __restrict__ x,
                                          const float* __restrict__ agg,
                                          float* __restrict__ out) {
    extern __shared__ __align__(16) char sm[];
    const int n0 = blockIdx.x * 128, c0 = blockIdx.y * 128;
    float acc[4][4][4] = {};
    gemm_pipe(g_fiT + (size_t)n0 * HS, HS, g_Tt + (size_t)c0 * HS, HS, HS, acc, sm);

    const int tid = threadIdx.x, lane = tid & 31, wid = tid >> 5;
    const int mBase = (wid >> 2) * 64, nBase = (wid & 3) * 32;
    const int r = lane >> 2, cc = (lane & 3) * 2;
    const float scale = agg[0] * (1.0f / (float)NN);
#pragma unroll
    for (int mf = 0; mf < 4; mf++)
#pragma unroll
        for (int e = 0; e < 2; e++) {
            const int n = n0 + mBase + mf * 16 + r + e * 8;
#pragma unroll
            for (int nf = 0; nf < 4; nf++) {
                const int c = c0 + nBase + nf * 8 + cc;
                const size_t i0 = (size_t)c * NN + n;
                const size_t i1 = (size_t)(c + 1) * NN + n;
                out[i0] = x[i0] + scale * acc[mf][nf][e * 2];
                out[i1] = x[i1] + scale * acc[mf][nf][e * 2 + 1];
            }
        }
}

// ---------------- launch ----------------
extern "C" void kernel_launch(void* const* d_in, const int* in_sizes, int n_in,
                              void* d_out, int out_size) {
    const float* features = (const float*)d_in[0];
    const float* Wi       = (const float*)d_in[1];
    const float* bi       = (const float*)d_in[2];
    const float* Wj       = (const float*)d_in[3];
    const float* bj       = (const float*)d_in[4];
    const float* agg      = (const float*)d_in[5];
    float* out = (float*)d_out;

    cudaFuncSetAttribute(k1, cudaFuncAttributeMaxDynamicSharedMemorySize, SMEM_TOT);
    cudaFuncSetAttribute(k2, cudaFuncAttributeMaxDynamicSharedMemorySize, SMEM_TOT);
    cudaFuncSetAttribute(k4, cudaFuncAttributeMaxDynamicSharedMemorySize, SMEM_TOT);

    k0_w<<<512, 256>>>(Wi, Wj);
    k_pre<<<dim3(NN / 32, CC / 32), dim3(32, 8)>>>(features);
    k1<<<dim3(81, 2), 256, SMEM_TOT>>>(bi, bj);
    k2<<<dim3(4, SPL), 256, SMEM_TOT>>>();
    kred<<<(HS * CC + 255) / 256, 256>>>();
    k4<<<dim3(81, 4), 256, SMEM_TOT>>>(features, agg, out);
}